// round 3
// baseline (speedup 1.0000x reference)
#include <cuda_runtime.h>
#include <cuda_fp16.h>
#include <cstdint>
#include <cstddef>

// Problem constants
#define BQ 8192      // batch rows      (GEMM M)
#define NQ 4096      // inner dim       (GEMM K)
#define KQ 11008     // output cols     (GEMM N)
#define NG 64        // quant groups along NQ

// GEMM tiling
#define BM 128
#define BN 256
#define BK 64
#define NKIT (NQ / BK)            // 64 mainloop iterations
#define NSTAGE 4
#define STAGE_A (BM * BK * 2)     // 16384 B
#define STAGE_B (BN * BK * 2)     // 32768 B
#define STAGE_BYTES (STAGE_A + STAGE_B)      // 49152 B
#define SMEM_TOTAL (NSTAGE * STAGE_BYTES)    // 196608 B

// ---------------------------------------------------------------------------
// Scratch (sanctioned __device__ globals)
// g_A[b,k] = fp16( x[b,k] * mu1[k] )
// g_W[n,k] = fp16( (Q[n,k] - zero[n,g])*scale[n,g]*mu2[n] )
// out = g_A @ g_W^T  (fp32 accumulate)
// ---------------------------------------------------------------------------
__device__ __align__(1024) __half g_A[(size_t)BQ * NQ];
__device__ __align__(1024) __half g_W[(size_t)KQ * NQ];

// ---------------------------------------------------------------------------
// Helpers
// ---------------------------------------------------------------------------
__device__ __forceinline__ uint32_t smem_u32(const void* p) {
    uint32_t a;
    asm("{ .reg .u64 t; cvta.to.shared.u64 t, %1; cvt.u32.u64 %0, t; }" : "=r"(a) : "l"(p));
    return a;
}

__device__ __forceinline__ void cp_async16(uint32_t saddr, const void* gaddr) {
    asm volatile("cp.async.cg.shared.global [%0], [%1], 16;" :: "r"(saddr), "l"(gaddr) : "memory");
}

__device__ __forceinline__ uint32_t pack_half2(float a, float b) {
    __half2 h = __halves2half2(__float2half_rn(a), __float2half_rn(b));
    return *reinterpret_cast<uint32_t*>(&h);
}

// ---------------------------------------------------------------------------
// Prep 1: g_A = fp16(x * mu1)
// ---------------------------------------------------------------------------
__global__ void prep_x_kernel(const float* __restrict__ x, const float* __restrict__ mu1) {
    int idx = blockIdx.x * blockDim.x + threadIdx.x;      // one per 4 elements
    const int total = BQ * NQ / 4;
    if (idx >= total) return;
    int n4 = idx & (NQ / 4 - 1);                          // NQ/4 = 1024 (pow2)

    float4 xv = reinterpret_cast<const float4*>(x)[idx];
    float4 mv = reinterpret_cast<const float4*>(mu1)[n4];
    uint2 v;
    v.x = pack_half2(xv.x * mv.x, xv.y * mv.y);
    v.y = pack_half2(xv.z * mv.z, xv.w * mv.w);
    reinterpret_cast<uint2*>(g_A)[idx] = v;
}

// ---------------------------------------------------------------------------
// Prep 2: g_W = fp16((Q - zero)*scale*mu2)
// ---------------------------------------------------------------------------
__global__ void prep_w_kernel(const int* __restrict__ Wq,
                              const float* __restrict__ zeros,
                              const float* __restrict__ scales,
                              const float* __restrict__ mu2) {
    int idx = blockIdx.x * blockDim.x + threadIdx.x;      // one per 4 elements
    const int total = KQ * NQ / 4;
    if (idx >= total) return;
    int k = idx >> 10;                                    // / (NQ/4)
    int n4 = idx & 1023;
    int g = n4 >> 4;                                      // (n4*4)/64

    int4 qv = reinterpret_cast<const int4*>(Wq)[idx];
    float z  = zeros[k * NG + g];
    float sc = scales[k * NG + g] * mu2[k];

    uint2 v;
    v.x = pack_half2(((float)qv.x - z) * sc, ((float)qv.y - z) * sc);
    v.y = pack_half2(((float)qv.z - z) * sc, ((float)qv.w - z) * sc);
    reinterpret_cast<uint2*>(g_W)[idx] = v;
}

// ---------------------------------------------------------------------------
// GEMM: out[BQ,KQ] = g_A[BQ,NQ] @ g_W[KQ,NQ]^T
// 256 threads (8 warps, 2x4), warp tile 64x64, mma.sync m16n8k16 f16->f32.
// ---------------------------------------------------------------------------
__global__ void __launch_bounds__(256, 1) gemm_kernel(float* __restrict__ out) {
    extern __shared__ __align__(1024) char smem[];
    const uint32_t sb = smem_u32(smem);
    const int tid = threadIdx.x;
    const int lane = tid & 31, wid = tid >> 5;
    const int wm = wid >> 2, wn = wid & 3;                // warp grid 2(M) x 4(N)
    const int mBase = blockIdx.y * BM;
    const int nBase = blockIdx.x * BN;

    // ---- cp.async geometry: thread t loads row (t/8 + 32*i), 16B segment t%8
    const int lrow = tid >> 3, lseg = tid & 7;
    const char* gA = reinterpret_cast<const char*>(g_A) +
                     ((size_t)(mBase + lrow) * NQ + (size_t)lseg * 8) * 2;
    const char* gB = reinterpret_cast<const char*>(g_W) +
                     ((size_t)(nBase + lrow) * NQ + (size_t)lseg * 8) * 2;
    // swizzled smem offset for (row=lrow, seg=lseg); +32 rows => +4096 B (XOR invariant)
    const uint32_t swb = ((uint32_t)(lrow * 128 + lseg * 16)) ^ (((uint32_t)lrow & 7u) << 4);

    auto load_stage = [&](int s, int kc) {
        uint32_t dA = sb + (uint32_t)s * STAGE_BYTES + swb;
        const char* srcA = gA + (size_t)kc * 128;
        #pragma unroll
        for (int i = 0; i < 4; i++)            // 128 A rows
            cp_async16(dA + (uint32_t)i * 4096u, srcA + (size_t)i * 32 * (NQ * 2));
        uint32_t dB = sb + (uint32_t)s * STAGE_BYTES + STAGE_A + swb;
        const char* srcB = gB + (size_t)kc * 128;
        #pragma unroll
        for (int i = 0; i < 8; i++)            // 256 W rows
            cp_async16(dB + (uint32_t)i * 4096u, srcB + (size_t)i * 32 * (NQ * 2));
        asm volatile("cp.async.commit_group;" ::: "memory");
    };

    // Prefill 3 stages
    #pragma unroll
    for (int s = 0; s < NSTAGE - 1; s++) load_stage(s, s);

    // Accumulators: 4 m-tiles x 8 n-tiles x 4 floats = 128 regs
    float acc[4][8][4];
    #pragma unroll
    for (int mt = 0; mt < 4; mt++)
        #pragma unroll
        for (int nt = 0; nt < 8; nt++)
            #pragma unroll
            for (int q = 0; q < 4; q++) acc[mt][nt][q] = 0.0f;

    // ldmatrix per-thread address components (SW128: addr = row*128 + (col ^ ((row&7)<<4)))
    const uint32_t xorv = ((uint32_t)lane & 7u) << 4;
    const uint32_t aRow = (uint32_t)(wm * 64 + (lane & 15)) * 128;   // (mt*16 multiple of 8 -> xor const)
    const uint32_t aColL = ((uint32_t)(lane >> 4)) << 4;             // 0 / 16
    const uint32_t bRowOff = (uint32_t)((lane & 7) + (((lane >> 4) & 1) << 3));
    const uint32_t bRow = ((uint32_t)wn * 64 + bRowOff) * 128;
    const uint32_t bColL = ((uint32_t)((lane >> 3) & 1)) << 4;       // 0 / 16

    for (int it = 0; it < NKIT; it++) {
        asm volatile("cp.async.wait_group 2;" ::: "memory");
        __syncthreads();
        if (it + NSTAGE - 1 < NKIT)
            load_stage((it + NSTAGE - 1) % NSTAGE, it + NSTAGE - 1);
        else
            asm volatile("cp.async.commit_group;" ::: "memory");  // keep group accounting aligned

        const uint32_t sA = sb + (uint32_t)(it % NSTAGE) * STAGE_BYTES;
        const uint32_t sBs = sA + STAGE_A;

        #pragma unroll
        for (int ks = 0; ks < 4; ks++) {
            uint32_t a[4][4], b[4][4];
            const uint32_t colA = (((uint32_t)ks * 32) + aColL) ^ xorv;
            const uint32_t colB = (((uint32_t)ks * 32) + bColL) ^ xorv;
            #pragma unroll
            for (int mt = 0; mt < 4; mt++) {
                uint32_t addr = sA + aRow + (uint32_t)mt * 2048u + colA;
                asm volatile("ldmatrix.sync.aligned.m8n8.x4.shared.b16 {%0,%1,%2,%3}, [%4];"
                             : "=r"(a[mt][0]), "=r"(a[mt][1]), "=r"(a[mt][2]), "=r"(a[mt][3])
                             : "r"(addr));
            }
            #pragma unroll
            for (int np = 0; np < 4; np++) {
                uint32_t addr = sBs + bRow + (uint32_t)np * 2048u + colB;
                asm volatile("ldmatrix.sync.aligned.m8n8.x4.shared.b16 {%0,%1,%2,%3}, [%4];"
                             : "=r"(b[np][0]), "=r"(b[np][1]), "=r"(b[np][2]), "=r"(b[np][3])
                             : "r"(addr));
            }
            #pragma unroll
            for (int mt = 0; mt < 4; mt++) {
                #pragma unroll
                for (int nt = 0; nt < 8; nt++) {
                    const uint32_t b0 = b[nt >> 1][(nt & 1) * 2];
                    const uint32_t b1 = b[nt >> 1][(nt & 1) * 2 + 1];
                    asm volatile(
                        "mma.sync.aligned.m16n8k16.row.col.f32.f16.f16.f32 "
                        "{%0,%1,%2,%3}, {%4,%5,%6,%7}, {%8,%9}, {%0,%1,%2,%3};"
                        : "+f"(acc[mt][nt][0]), "+f"(acc[mt][nt][1]),
                          "+f"(acc[mt][nt][2]), "+f"(acc[mt][nt][3])
                        : "r"(a[mt][0]), "r"(a[mt][1]), "r"(a[mt][2]), "r"(a[mt][3]),
                          "r"(b0), "r"(b1));
                }
            }
        }
    }

    // Epilogue: direct fp32 stores (float2 per mma quad-pair)
    const int mRow = mBase + wm * 64 + (lane >> 2);
    const int nCol = nBase + wn * 64 + (lane & 3) * 2;
    #pragma unroll
    for (int mt = 0; mt < 4; mt++) {
        #pragma unroll
        for (int nt = 0; nt < 8; nt++) {
            float* p = out + (size_t)(mRow + mt * 16) * KQ + (nCol + nt * 8);
            *reinterpret_cast<float2*>(p) = make_float2(acc[mt][nt][0], acc[mt][nt][1]);
            *reinterpret_cast<float2*>(p + (size_t)8 * KQ) =
                make_float2(acc[mt][nt][2], acc[mt][nt][3]);
        }
    }
}

// ---------------------------------------------------------------------------
// Launch
// ---------------------------------------------------------------------------
extern "C" void kernel_launch(void* const* d_in, const int* in_sizes, int n_in,
                              void* d_out, int out_size) {
    const float* x      = (const float*)d_in[0];
    const int*   Wq     = (const int*)d_in[1];
    const float* zeros  = (const float*)d_in[2];
    const float* scales = (const float*)d_in[3];
    const float* mu1    = (const float*)d_in[4];
    const float* mu2    = (const float*)d_in[5];
    float* out = (float*)d_out;

    cudaFuncSetAttribute(gemm_kernel, cudaFuncAttributeMaxDynamicSharedMemorySize, SMEM_TOTAL);

    prep_x_kernel<<<(BQ * NQ / 4 + 255) / 256, 256>>>(x, mu1);
    prep_w_kernel<<<(KQ * NQ / 4 + 255) / 256, 256>>>(Wq, zeros, scales, mu2);

    dim3 grid(KQ / BN, BQ / BM);   // (43, 64)
    gemm_kernel<<<grid, 256, SMEM_TOTAL>>>(out);
}

// round 4
// speedup vs baseline: 1.0967x; 1.0967x over previous
#include <cuda_runtime.h>
#include <cuda_fp16.h>
#include <cstdint>
#include <cstddef>

// Problem constants
#define BQ 8192      // batch rows      (GEMM M)
#define NQ 4096      // inner dim       (GEMM K)
#define KQ 11008     // output cols     (GEMM N)
#define NG 64        // quant groups along NQ

// GEMM tiling: 128x128 CTA tile, 2 CTAs/SM for cross-CTA bubble overlap
#define BM 128
#define BN 128
#define BK 64
#define NKIT (NQ / BK)            // 64 mainloop iterations
#define NSTAGE 3
#define STAGE_A (BM * BK * 2)     // 16384 B
#define STAGE_B (BN * BK * 2)     // 16384 B
#define STAGE_BYTES (STAGE_A + STAGE_B)      // 32768 B
#define SMEM_TOTAL (NSTAGE * STAGE_BYTES)    // 98304 B

// ---------------------------------------------------------------------------
// Scratch (sanctioned __device__ globals)
// g_A[b,k] = fp16( x[b,k] * mu1[k] )
// g_W[n,k] = fp16( (Q[n,k] - zero[n,g])*scale[n,g]*mu2[n] )
// ---------------------------------------------------------------------------
__device__ __align__(1024) __half g_A[(size_t)BQ * NQ];
__device__ __align__(1024) __half g_W[(size_t)KQ * NQ];

__device__ __forceinline__ uint32_t smem_u32(const void* p) {
    uint32_t a;
    asm("{ .reg .u64 t; cvta.to.shared.u64 t, %1; cvt.u32.u64 %0, t; }" : "=r"(a) : "l"(p));
    return a;
}

__device__ __forceinline__ void cp_async16(uint32_t saddr, const void* gaddr) {
    asm volatile("cp.async.cg.shared.global [%0], [%1], 16;" :: "r"(saddr), "l"(gaddr) : "memory");
}

__device__ __forceinline__ uint32_t pack_half2(float a, float b) {
    __half2 h = __halves2half2(__float2half_rn(a), __float2half_rn(b));
    return *reinterpret_cast<uint32_t*>(&h);
}

// ---------------------------------------------------------------------------
// Fused prep: blocks [0, XB) build g_A; blocks [XB, XB+WB) build g_W.
// ---------------------------------------------------------------------------
#define XB ((BQ * NQ / 4) / 256)                 // 32768 blocks
#define WB ((KQ * NQ / 4) / 256)                 // 44032 blocks

__global__ void prep_kernel(const float* __restrict__ x, const float* __restrict__ mu1,
                            const int* __restrict__ Wq, const float* __restrict__ zeros,
                            const float* __restrict__ scales, const float* __restrict__ mu2) {
    int b = blockIdx.x;
    if (b < XB) {
        int idx = b * 256 + threadIdx.x;                  // one per 4 elements of x
        int n4 = idx & (NQ / 4 - 1);
        float4 xv = reinterpret_cast<const float4*>(x)[idx];
        float4 mv = reinterpret_cast<const float4*>(mu1)[n4];
        uint2 v;
        v.x = pack_half2(xv.x * mv.x, xv.y * mv.y);
        v.y = pack_half2(xv.z * mv.z, xv.w * mv.w);
        reinterpret_cast<uint2*>(g_A)[idx] = v;
    } else {
        int idx = (b - XB) * 256 + threadIdx.x;           // one per 4 elements of W
        int k = idx >> 10;                                // / (NQ/4)
        int n4 = idx & 1023;
        int g = n4 >> 4;                                  // (n4*4)/64
        int4 qv = reinterpret_cast<const int4*>(Wq)[idx];
        float z  = zeros[k * NG + g];
        float sc = scales[k * NG + g] * mu2[k];
        uint2 v;
        v.x = pack_half2(((float)qv.x - z) * sc, ((float)qv.y - z) * sc);
        v.y = pack_half2(((float)qv.z - z) * sc, ((float)qv.w - z) * sc);
        reinterpret_cast<uint2*>(g_W)[idx] = v;
    }
}

// ---------------------------------------------------------------------------
// GEMM: out[BQ,KQ] = g_A @ g_W^T.  8 warps (2x4), warp tile 64x32,
// mma.sync m16n8k16 f16->f32, 3-stage cp.async ring, 2 CTAs/SM.
// ---------------------------------------------------------------------------
__global__ void __launch_bounds__(256, 2) gemm_kernel(float* __restrict__ out) {
    extern __shared__ __align__(1024) char smem[];
    const uint32_t sb = smem_u32(smem);
    const int tid = threadIdx.x;
    const int lane = tid & 31, wid = tid >> 5;
    const int wm = wid >> 2, wn = wid & 3;               // warps: 2(M) x 4(N)
    const int mBase = blockIdx.x * BM;                   // m fast-varying (L2 reuse of W)
    const int nBase = blockIdx.y * BN;

    // cp.async geometry: thread t -> row (t/8 + 32*i), 16B segment t%8
    const int lrow = tid >> 3, lseg = tid & 7;
    const char* gA = reinterpret_cast<const char*>(g_A) +
                     ((size_t)(mBase + lrow) * NQ + (size_t)lseg * 8) * 2;
    const char* gB = reinterpret_cast<const char*>(g_W) +
                     ((size_t)(nBase + lrow) * NQ + (size_t)lseg * 8) * 2;
    const uint32_t swb = ((uint32_t)(lrow * 128 + lseg * 16)) ^ (((uint32_t)lrow & 7u) << 4);

    auto load_stage = [&](int s, int kc) {
        uint32_t dA = sb + (uint32_t)s * STAGE_BYTES + swb;
        const char* srcA = gA + (size_t)kc * 128;
        #pragma unroll
        for (int i = 0; i < 4; i++)          // 128 A rows
            cp_async16(dA + (uint32_t)i * 4096u, srcA + (size_t)i * 32 * (NQ * 2));
        uint32_t dB = dA + STAGE_A;
        const char* srcB = gB + (size_t)kc * 128;
        #pragma unroll
        for (int i = 0; i < 4; i++)          // 128 W rows
            cp_async16(dB + (uint32_t)i * 4096u, srcB + (size_t)i * 32 * (NQ * 2));
        asm volatile("cp.async.commit_group;" ::: "memory");
    };

    // Prefill 2 stages
    load_stage(0, 0);
    load_stage(1, 1);

    // Accumulators: 4 m-tiles x 4 n-tiles x 4 = 64 regs
    float acc[4][4][4];
    #pragma unroll
    for (int mt = 0; mt < 4; mt++)
        #pragma unroll
        for (int nt = 0; nt < 4; nt++)
            #pragma unroll
            for (int q = 0; q < 4; q++) acc[mt][nt][q] = 0.0f;

    // ldmatrix address components (SW128 swizzle keyed on row&7)
    const uint32_t xorv = ((uint32_t)lane & 7u) << 4;
    const uint32_t aRow = (uint32_t)(wm * 64 + (lane & 15)) * 128;
    const uint32_t aColL = ((uint32_t)(lane >> 4)) << 4;              // 0 / 16
    const uint32_t bRowOff = (uint32_t)((lane & 7) + (((lane >> 4) & 1) << 3));
    const uint32_t bRow = ((uint32_t)wn * 32 + bRowOff) * 128;
    const uint32_t bColL = ((uint32_t)((lane >> 3) & 1)) << 4;        // 0 / 16

    for (int it = 0; it < NKIT; it++) {
        asm volatile("cp.async.wait_group 1;" ::: "memory");
        __syncthreads();
        if (it + 2 < NKIT)
            load_stage((it + 2) % NSTAGE, it + 2);
        else
            asm volatile("cp.async.commit_group;" ::: "memory");   // keep accounting aligned

        const uint32_t sA = sb + (uint32_t)(it % NSTAGE) * STAGE_BYTES;
        const uint32_t sBs = sA + STAGE_A;

        #pragma unroll
        for (int ks = 0; ks < 4; ks++) {
            uint32_t a[4][4], b[2][4];
            const uint32_t colA = (((uint32_t)ks * 32) + aColL) ^ xorv;
            const uint32_t colB = (((uint32_t)ks * 32) + bColL) ^ xorv;
            #pragma unroll
            for (int mt = 0; mt < 4; mt++) {
                uint32_t addr = sA + aRow + (uint32_t)mt * 2048u + colA;
                asm volatile("ldmatrix.sync.aligned.m8n8.x4.shared.b16 {%0,%1,%2,%3}, [%4];"
                             : "=r"(a[mt][0]), "=r"(a[mt][1]), "=r"(a[mt][2]), "=r"(a[mt][3])
                             : "r"(addr));
            }
            #pragma unroll
            for (int np = 0; np < 2; np++) {
                uint32_t addr = sBs + bRow + (uint32_t)np * 2048u + colB;
                asm volatile("ldmatrix.sync.aligned.m8n8.x4.shared.b16 {%0,%1,%2,%3}, [%4];"
                             : "=r"(b[np][0]), "=r"(b[np][1]), "=r"(b[np][2]), "=r"(b[np][3])
                             : "r"(addr));
            }
            #pragma unroll
            for (int mt = 0; mt < 4; mt++) {
                #pragma unroll
                for (int nt = 0; nt < 4; nt++) {
                    const uint32_t b0 = b[nt >> 1][(nt & 1) * 2];
                    const uint32_t b1 = b[nt >> 1][(nt & 1) * 2 + 1];
                    asm volatile(
                        "mma.sync.aligned.m16n8k16.row.col.f32.f16.f16.f32 "
                        "{%0,%1,%2,%3}, {%4,%5,%6,%7}, {%8,%9}, {%0,%1,%2,%3};"
                        : "+f"(acc[mt][nt][0]), "+f"(acc[mt][nt][1]),
                          "+f"(acc[mt][nt][2]), "+f"(acc[mt][nt][3])
                        : "r"(a[mt][0]), "r"(a[mt][1]), "r"(a[mt][2]), "r"(a[mt][3]),
                          "r"(b0), "r"(b1));
                }
            }
        }
    }

    // Epilogue: fp32 stores
    const int mRow = mBase + wm * 64 + (lane >> 2);
    const int nCol = nBase + wn * 32 + (lane & 3) * 2;
    #pragma unroll
    for (int mt = 0; mt < 4; mt++) {
        #pragma unroll
        for (int nt = 0; nt < 4; nt++) {
            float* p = out + (size_t)(mRow + mt * 16) * KQ + (nCol + nt * 8);
            *reinterpret_cast<float2*>(p) = make_float2(acc[mt][nt][0], acc[mt][nt][1]);
            *reinterpret_cast<float2*>(p + (size_t)8 * KQ) =
                make_float2(acc[mt][nt][2], acc[mt][nt][3]);
        }
    }
}

// ---------------------------------------------------------------------------
// Launch
// ---------------------------------------------------------------------------
extern "C" void kernel_launch(void* const* d_in, const int* in_sizes, int n_in,
                              void* d_out, int out_size) {
    const float* x      = (const float*)d_in[0];
    const int*   Wq     = (const int*)d_in[1];
    const float* zeros  = (const float*)d_in[2];
    const float* scales = (const float*)d_in[3];
    const float* mu1    = (const float*)d_in[4];
    const float* mu2    = (const float*)d_in[5];
    float* out = (float*)d_out;

    cudaFuncSetAttribute(gemm_kernel, cudaFuncAttributeMaxDynamicSharedMemorySize, SMEM_TOTAL);

    prep_kernel<<<XB + WB, 256>>>(x, mu1, Wq, zeros, scales, mu2);

    dim3 grid(BQ / BM, KQ / BN);   // (64, 86), m fast-varying
    gemm_kernel<<<grid, 256, SMEM_TOTAL>>>(out);
}